// round 13
// baseline (speedup 1.0000x reference)
#include <cuda_runtime.h>

// PSRoIPool (R-FCN style), fp32.
// features: [B=4, C=490, H=38, W=38], rois: [R=256, 5], out: [R,10,7,7]
// c = (d*P + ph)*P + pw
//
// Numerics (locked, PASS @ rel_err 2.845666e-08):
//  - xs/ys/xe/ye exact (integer/16); bin = roi * RN(1/7) (XLA reciprocal-
//    multiply strength reduction, NOT fdiv)
//  - edges via fmaf; two-level ascending summation (rows of w, then h)
//
// Perf (R13): R12 was block-latency bound — 3.3 blocks/SM, each a serial
// [stage 23KB -> barrier -> gather] chain. Split block = (batch, channel):
// 1960 blocks (13.2/SM) each staging ONE 5776B plane (1.4 float4/thread,
// one DRAM round trip). Threads whose ROI batch != b exit after the
// barrier. Every plane still read exactly once; 4x block concurrency
// pipelines stage latency across blocks.

#define P_ 7
#define D_ 10
#define H_ 38
#define W_ 38
#define C_ 490
#define R_ 256
#define B_ 4
#define PLANE_ (H_ * W_)          // 1444 floats, 5776 B
#define PLANE4_ (PLANE_ / 4)      // 361 float4
#define SCALE_ 0.0625f

__global__ __launch_bounds__(256) void psroi_kernel(
    const float* __restrict__ feat,
    const float* __restrict__ rois,
    float* __restrict__ out)
{
    __shared__ float sf[PLANE_];                 // 5776 B

    int blk   = blockIdx.x;                      // b*C_ + c : adjacent blocks
    int b_blk = blk / C_;                        //   stream adjacent planes
    int c     = blk - b_blk * C_;
    int tid   = threadIdx.x;                     // 0..255 == ROI index

    // ---- stage feat[b_blk][c][:,:] into smem, coalesced float4 ----
    const float4* src = (const float4*)feat + ((size_t)b_blk * C_ + c) * PLANE4_;
    float4*       dst = (float4*)sf;
    for (int k = tid; k < PLANE4_; k += 256)
        dst[k] = src[k];
    __syncthreads();

    // ---- one ROI per thread; only batch-matching threads proceed ----
    const float* roi = rois + tid * 5;
    int b = (int)roi[0];
    if (b != b_blk) return;

    int pw = c % P_;                // column bin (bin_w, xs)
    int ph = (c / P_) % P_;         // row bin    (bin_h, ys)

    // jnp.round == round-half-to-even == rintf (RN); *0.0625 exact
    float xs = __fmul_rn(rintf(roi[1]), SCALE_);
    float ys = __fmul_rn(rintf(roi[2]), SCALE_);
    float xe = __fmul_rn(rintf(__fadd_rn(roi[3], 1.0f)), SCALE_);
    float ye = __fmul_rn(rintf(__fadd_rn(roi[4], 1.0f)), SCALE_);

    const float RECIP7 = 1.0f / 7.0f;   // RN(1/7)
    float bin_w = __fmul_rn(fmaxf(__fadd_rn(xe, -xs), 0.1f), RECIP7);
    float bin_h = __fmul_rn(fmaxf(__fadd_rn(ye, -ys), 0.1f), RECIP7);

    // edges: single-rounding FMA; clip to [0,H]/[0,W]
    float hs = floorf(fmaf((float) ph,      bin_h, ys));
    float he = ceilf (fmaf((float)(ph + 1), bin_h, ys));
    float ws = floorf(fmaf((float) pw,      bin_w, xs));
    float we = ceilf (fmaf((float)(pw + 1), bin_w, xs));

    int hstart = (int)fminf(fmaxf(hs, 0.0f), (float)H_);
    int hend   = (int)fminf(fmaxf(he, 0.0f), (float)H_);
    int wstart = (int)fminf(fmaxf(ws, 0.0f), (float)W_);
    int wend   = (int)fminf(fmaxf(we, 0.0f), (float)W_);

    int hspan = hend - hstart;          // 0..4 (roi wh <= 256 -> span <= 4)
    int wspan = wend - wstart;          // 0..4

    const float* base = sf + hstart * W_ + wstart;

    // predicated 4x4 gather from smem, exact two-level ascending reduce
    float v[4][4];
    #pragma unroll
    for (int i = 0; i < 4; ++i) {
        #pragma unroll
        for (int j = 0; j < 4; ++j) {
            bool valid = (i < hspan) && (j < wspan);
            v[i][j] = valid ? base[i * W_ + j] : 0.0f;
        }
    }

    float sum = 0.0f;
    #pragma unroll
    for (int i = 0; i < 4; ++i) {
        float rsum = 0.0f;
        #pragma unroll
        for (int j = 0; j < 4; ++j)
            rsum = __fadd_rn(rsum, v[i][j]);   // ascending w
        sum = __fadd_rn(sum, rsum);            // ascending h
    }

    int cnt = hspan * wspan;
    // out[r][d][ph][pw] = out[tid*490 + c]
    out[tid * C_ + c] = (cnt > 0) ? __fdiv_rn(sum, (float)cnt) : 0.0f;
}

extern "C" void kernel_launch(void* const* d_in, const int* in_sizes, int n_in,
                              void* d_out, int out_size)
{
    const float* feat = (const float*)d_in[0];
    const float* rois = (const float*)d_in[1];
    float* out = (float*)d_out;

    psroi_kernel<<<B_ * C_, 256>>>(feat, rois, out);   // 1960 blocks
}

// round 14
// speedup vs baseline: 1.0469x; 1.0469x over previous
#include <cuda_runtime.h>

// PSRoIPool (R-FCN style), fp32.
// features: [B=4, C=490, H=38, W=38], rois: [R=256, 5], out: [R,10,7,7]
// c = (d*P + ph)*P + pw
//
// Numerics (locked, PASS @ rel_err 2.845666e-08):
//  - xs/ys/xe/ye exact (integer/16); bin = roi * RN(1/7) (XLA reciprocal-
//    multiply strength reduction, NOT fdiv)
//  - edges via fmaf; two-level ascending summation (rows of w, then h)
//
// Perf history: R12 (block=c, 490 blocks) 7.14us — block-latency bound at
// 3.3 blocks/SM. R13 (block=(b,c), 1960 blocks) 8.58us — REGRESSED: 1960 >
// 1184 resident ceiling -> 1.65 waves, partial-wave tail + 4x per-block
// overhead. R14: block = (batch-PAIR, c) -> 980 blocks: single wave, 6.6
// blocks/SM (2x R12 overlap), stage 2 planes (11.5 KB, half the latency).
// Window math hoisted before the barrier to hide under staging loads.
// Every plane still read exactly once.

#define P_ 7
#define D_ 10
#define H_ 38
#define W_ 38
#define C_ 490
#define R_ 256
#define B_ 4
#define PLANE_ (H_ * W_)          // 1444 floats, 5776 B
#define PLANE4_ (PLANE_ / 4)      // 361 float4
#define SCALE_ 0.0625f

__global__ __launch_bounds__(256) void psroi_kernel(
    const float* __restrict__ feat,
    const float* __restrict__ rois,
    float* __restrict__ out)
{
    __shared__ float sf[2 * PLANE_];             // 11552 B

    int blk   = blockIdx.x;                      // pair*C_ + c
    int pair  = blk / C_;                        // 0: batches 0,1  1: 2,3
    int c     = blk - pair * C_;
    int tid   = threadIdx.x;                     // 0..255 == ROI index
    int b0    = 2 * pair;

    // ---- stage feat[b0][c] and feat[b0+1][c] into smem (coalesced) ----
    const float4* src = (const float4*)feat;
    float4*       dst = (float4*)sf;
    #pragma unroll
    for (int k = tid; k < 2 * PLANE4_; k += 256) {
        int bb = (k >= PLANE4_);                 // 0 or 1
        int q  = k - bb * PLANE4_;
        dst[k] = src[((size_t)(b0 + bb) * C_ + c) * PLANE4_ + q];
    }

    // ---- window math (independent of smem: overlaps staging latency) ----
    const float* roi = rois + tid * 5;
    int b = (int)roi[0];

    int pw = c % P_;                // column bin (bin_w, xs)
    int ph = (c / P_) % P_;         // row bin    (bin_h, ys)

    // jnp.round == round-half-to-even == rintf (RN); *0.0625 exact
    float xs = __fmul_rn(rintf(roi[1]), SCALE_);
    float ys = __fmul_rn(rintf(roi[2]), SCALE_);
    float xe = __fmul_rn(rintf(__fadd_rn(roi[3], 1.0f)), SCALE_);
    float ye = __fmul_rn(rintf(__fadd_rn(roi[4], 1.0f)), SCALE_);

    const float RECIP7 = 1.0f / 7.0f;   // RN(1/7)
    float bin_w = __fmul_rn(fmaxf(__fadd_rn(xe, -xs), 0.1f), RECIP7);
    float bin_h = __fmul_rn(fmaxf(__fadd_rn(ye, -ys), 0.1f), RECIP7);

    // edges: single-rounding FMA; clip to [0,H]/[0,W]
    float hs = floorf(fmaf((float) ph,      bin_h, ys));
    float he = ceilf (fmaf((float)(ph + 1), bin_h, ys));
    float ws = floorf(fmaf((float) pw,      bin_w, xs));
    float we = ceilf (fmaf((float)(pw + 1), bin_w, xs));

    int hstart = (int)fminf(fmaxf(hs, 0.0f), (float)H_);
    int hend   = (int)fminf(fmaxf(he, 0.0f), (float)H_);
    int wstart = (int)fminf(fmaxf(ws, 0.0f), (float)W_);
    int wend   = (int)fminf(fmaxf(we, 0.0f), (float)W_);

    int hspan = hend - hstart;          // 0..4 (roi wh <= 256 -> span <= 4)
    int wspan = wend - wstart;          // 0..4

    __syncthreads();

    // ---- only threads whose ROI batch is in this pair proceed ----
    if ((b >> 1) != pair) return;

    const float* base = sf + (b & 1) * PLANE_ + hstart * W_ + wstart;

    // predicated 4x4 gather from smem, exact two-level ascending reduce
    float v[4][4];
    #pragma unroll
    for (int i = 0; i < 4; ++i) {
        #pragma unroll
        for (int j = 0; j < 4; ++j) {
            bool valid = (i < hspan) && (j < wspan);
            v[i][j] = valid ? base[i * W_ + j] : 0.0f;
        }
    }

    float sum = 0.0f;
    #pragma unroll
    for (int i = 0; i < 4; ++i) {
        float rsum = 0.0f;
        #pragma unroll
        for (int j = 0; j < 4; ++j)
            rsum = __fadd_rn(rsum, v[i][j]);   // ascending w
        sum = __fadd_rn(sum, rsum);            // ascending h
    }

    int cnt = hspan * wspan;
    // out[r][d][ph][pw] = out[tid*490 + c]
    out[tid * C_ + c] = (cnt > 0) ? __fdiv_rn(sum, (float)cnt) : 0.0f;
}

extern "C" void kernel_launch(void* const* d_in, const int* in_sizes, int n_in,
                              void* d_out, int out_size)
{
    const float* feat = (const float*)d_in[0];
    const float* rois = (const float*)d_in[1];
    float* out = (float*)d_out;

    psroi_kernel<<<2 * C_, 256>>>(feat, rois, out);   // 980 blocks, 1 wave
}